// round 4
// baseline (speedup 1.0000x reference)
#include <cuda_runtime.h>

// Problem constants
#define BB 16
#define CC 512
#define TT 1024
#define NH 8
#define HD 64

// Scratch (static device globals — allocation-free per harness rules)
__device__ float g_q[(size_t)BB * NH * TT * HD];
__device__ float g_k[(size_t)BB * NH * TT * HD];
__device__ float g_v[(size_t)BB * NH * TT * HD];
__device__ float g_att[(size_t)BB * NH * TT * HD];
__device__ float g_orot[(size_t)BB * CC * TT];

// ---------------------------------------------------------------------------
// Kernel 1: QKV projection GEMM.
// qkv[b][o][t] = sum_c w_qkv[o][c] * x[b][c][t] + b_qkv[o]
// Epilogue splits heads: which = o/512, ch = o%512, nh = ch%8, d = ch/8,
// stores to g_{q,k,v}[b][nh][t][d].
// Tile: BM=64 (o), BN=64 (t), BK=16 (c). 256 threads, 4x4 per thread.
// ---------------------------------------------------------------------------
__global__ __launch_bounds__(256) void qkv_gemm_kernel(
    const float* __restrict__ x, const float* __restrict__ w,
    const float* __restrict__ bias) {
  __shared__ float As[16][65];   // w^T tile (k-major rows)
  __shared__ float Bs[16][64];   // x tile
  const int b  = blockIdx.z;
  const int bm = blockIdx.y * 64;
  const int bn = blockIdx.x * 64;
  const int tid = threadIdx.x;
  const int tx = tid & 15, ty = tid >> 4;
  const int a_m = tid >> 2;
  const int a_k = (tid & 3) << 2;
  const int b_k = tid >> 4;
  const int b_n = (tid & 15) << 2;
  const float* xb = x + (size_t)b * CC * TT;

  float acc[4][4];
#pragma unroll
  for (int r = 0; r < 4; r++)
#pragma unroll
    for (int c = 0; c < 4; c++) acc[r][c] = 0.f;

  for (int k0 = 0; k0 < CC; k0 += 16) {
    float4 av = *(const float4*)(w + (size_t)(bm + a_m) * CC + k0 + a_k);
    As[a_k + 0][a_m] = av.x;
    As[a_k + 1][a_m] = av.y;
    As[a_k + 2][a_m] = av.z;
    As[a_k + 3][a_m] = av.w;
    *(float4*)(&Bs[b_k][b_n]) =
        *(const float4*)(xb + (size_t)(k0 + b_k) * TT + bn + b_n);
    __syncthreads();
#pragma unroll
    for (int k = 0; k < 16; k++) {
      float a0 = As[k][ty * 4 + 0];
      float a1 = As[k][ty * 4 + 1];
      float a2 = As[k][ty * 4 + 2];
      float a3 = As[k][ty * 4 + 3];
      float4 bv = *(const float4*)(&Bs[k][tx * 4]);
      acc[0][0] += a0 * bv.x; acc[0][1] += a0 * bv.y;
      acc[0][2] += a0 * bv.z; acc[0][3] += a0 * bv.w;
      acc[1][0] += a1 * bv.x; acc[1][1] += a1 * bv.y;
      acc[1][2] += a1 * bv.z; acc[1][3] += a1 * bv.w;
      acc[2][0] += a2 * bv.x; acc[2][1] += a2 * bv.y;
      acc[2][2] += a2 * bv.z; acc[2][3] += a2 * bv.w;
      acc[3][0] += a3 * bv.x; acc[3][1] += a3 * bv.y;
      acc[3][2] += a3 * bv.z; acc[3][3] += a3 * bv.w;
    }
    __syncthreads();
  }

#pragma unroll
  for (int r = 0; r < 4; r++) {
    const int o = bm + ty * 4 + r;
    const float bi = __ldg(bias + o);
    const int which = o >> 9;
    const int ch = o & 511;
    const int nh = ch & 7;
    const int d  = ch >> 3;
    float* dst = (which == 0) ? g_q : (which == 1) ? g_k : g_v;
    const size_t base = (((size_t)b * NH + nh) * TT) * HD + d;
#pragma unroll
    for (int c = 0; c < 4; c++) {
      const int t = bn + tx * 4 + c;
      dst[base + (size_t)t * HD] = acc[r][c] + bi;
    }
  }
}

// ---------------------------------------------------------------------------
// Kernel 2: in-place SO(2) rotation on q, k, v.
// One thread per (which, b, nh, t) row of 64 floats; pairs are adjacent dims.
// mat layout: [T][32][2][2] -> float4 (m00, m01, m10, m11) per pair.
// ---------------------------------------------------------------------------
__global__ __launch_bounds__(128) void rotary_qkv_kernel(
    const float* __restrict__ mq, const float* __restrict__ mk,
    const float* __restrict__ mv) {
  const int which = blockIdx.y;
  float* buf = (which == 0) ? g_q : (which == 1) ? g_k : g_v;
  const float* mat = (which == 0) ? mq : (which == 1) ? mk : mv;
  const int row = blockIdx.x * blockDim.x + threadIdx.x;  // 0..131071
  const int t = row & (TT - 1);
  float4* p = (float4*)(buf + (size_t)row * HD);
  const float4* m = (const float4*)(mat + (size_t)t * 128);
#pragma unroll
  for (int i = 0; i < 16; i++) {  // each float4 holds 2 rotation pairs
    float4 v  = p[i];
    float4 m0 = m[2 * i];
    float4 m1 = m[2 * i + 1];
    float4 o;
    o.x = m0.x * v.x + m0.y * v.y;
    o.y = m0.z * v.x + m0.w * v.y;
    o.z = m1.x * v.z + m1.y * v.w;
    o.w = m1.z * v.z + m1.w * v.w;
    p[i] = o;
  }
}

// ---------------------------------------------------------------------------
// Kernel 3: flash-style attention per (b*nh, q-tile of 64).
// Online softmax; 256 threads; per-thread 4x4 register tiles.
// Dynamic smem: Qs[64][64] (natural, pre-scaled), Ks[64][65] (transposed),
// Vs[64][64] (natural), Ps[64][68].
// ---------------------------------------------------------------------------
extern __shared__ float attn_sm[];

__global__ __launch_bounds__(256) void attn_kernel() {
  float* Qs = attn_sm;             // 64*64 = 4096
  float* Ks = Qs + 64 * 64;        // 64*65 = 4160 (transposed: [d][j])
  float* Vs = Ks + 64 * 65;        // 64*64 = 4096
  float* Ps = Vs + 64 * 64;        // 64*68 = 4352
  const int bh = blockIdx.y;       // b*NH + nh
  const int qb = blockIdx.x * 64;
  const int tid = threadIdx.x;
  const int tx = tid & 15, ty = tid >> 4;
  const float* Qg = g_q + ((size_t)bh * TT + qb) * HD;
  const float* Kg = g_k + (size_t)bh * TT * HD;
  const float* Vg = g_v + (size_t)bh * TT * HD;
  const float scale = 0.125f;  // 1/sqrt(64)

  // Load Q tile (natural layout), folded softmax scale.
  {
    const int r0 = tid >> 4;
    const int d0 = (tid & 15) << 2;
#pragma unroll
    for (int it = 0; it < 4; it++) {
      const int row = r0 + it * 16;
      float4 v = *(const float4*)(Qg + (size_t)row * HD + d0);
      v.x *= scale; v.y *= scale; v.z *= scale; v.w *= scale;
      *(float4*)(Qs + row * 64 + d0) = v;
    }
  }

  float m[4], l[4], o[4][4];
#pragma unroll
  for (int r = 0; r < 4; r++) {
    m[r] = -1e30f;
    l[r] = 0.f;
#pragma unroll
    for (int c = 0; c < 4; c++) o[r][c] = 0.f;
  }

  for (int kb = 0; kb < TT; kb += 64) {
    __syncthreads();  // previous PV done; Qs visible on first iteration
    // Load K tile transposed, V tile natural.
    {
      const int r0 = tid >> 4;
      const int d0 = (tid & 15) << 2;
#pragma unroll
      for (int it = 0; it < 4; it++) {
        const int row = r0 + it * 16;
        float4 kv = *(const float4*)(Kg + (size_t)(kb + row) * HD + d0);
        Ks[(d0 + 0) * 65 + row] = kv.x;
        Ks[(d0 + 1) * 65 + row] = kv.y;
        Ks[(d0 + 2) * 65 + row] = kv.z;
        Ks[(d0 + 3) * 65 + row] = kv.w;
        float4 vv = *(const float4*)(Vg + (size_t)(kb + row) * HD + d0);
        *(float4*)(Vs + row * 64 + d0) = vv;
      }
    }
    __syncthreads();

    // S = Q * K^T (scaled)
    float s[4][4];
#pragma unroll
    for (int r = 0; r < 4; r++)
#pragma unroll
      for (int c = 0; c < 4; c++) s[r][c] = 0.f;
#pragma unroll 16
    for (int d = 0; d < 64; d++) {
      float a0 = Qs[(ty * 4 + 0) * 64 + d];
      float a1 = Qs[(ty * 4 + 1) * 64 + d];
      float a2 = Qs[(ty * 4 + 2) * 64 + d];
      float a3 = Qs[(ty * 4 + 3) * 64 + d];
      float b0 = Ks[d * 65 + tx * 4 + 0];
      float b1 = Ks[d * 65 + tx * 4 + 1];
      float b2 = Ks[d * 65 + tx * 4 + 2];
      float b3 = Ks[d * 65 + tx * 4 + 3];
      s[0][0] += a0 * b0; s[0][1] += a0 * b1; s[0][2] += a0 * b2; s[0][3] += a0 * b3;
      s[1][0] += a1 * b0; s[1][1] += a1 * b1; s[1][2] += a1 * b2; s[1][3] += a1 * b3;
      s[2][0] += a2 * b0; s[2][1] += a2 * b1; s[2][2] += a2 * b2; s[2][3] += a2 * b3;
      s[3][0] += a3 * b0; s[3][1] += a3 * b1; s[3][2] += a3 * b2; s[3][3] += a3 * b3;
    }

    // Online softmax update (row stats replicated across the 16 tx lanes).
#pragma unroll
    for (int r = 0; r < 4; r++) {
      float rmax = fmaxf(fmaxf(s[r][0], s[r][1]), fmaxf(s[r][2], s[r][3]));
      rmax = fmaxf(rmax, __shfl_xor_sync(0xffffffffu, rmax, 1));
      rmax = fmaxf(rmax, __shfl_xor_sync(0xffffffffu, rmax, 2));
      rmax = fmaxf(rmax, __shfl_xor_sync(0xffffffffu, rmax, 4));
      rmax = fmaxf(rmax, __shfl_xor_sync(0xffffffffu, rmax, 8));
      const float mnew = fmaxf(m[r], rmax);
      const float alpha = __expf(m[r] - mnew);
      float rsum = 0.f;
#pragma unroll
      for (int c = 0; c < 4; c++) {
        const float p = __expf(s[r][c] - mnew);
        s[r][c] = p;
        rsum += p;
      }
      rsum += __shfl_xor_sync(0xffffffffu, rsum, 1);
      rsum += __shfl_xor_sync(0xffffffffu, rsum, 2);
      rsum += __shfl_xor_sync(0xffffffffu, rsum, 4);
      rsum += __shfl_xor_sync(0xffffffffu, rsum, 8);
      l[r] = l[r] * alpha + rsum;
      m[r] = mnew;
#pragma unroll
      for (int c = 0; c < 4; c++) o[r][c] *= alpha;
      *(float4*)(Ps + (ty * 4 + r) * 68 + tx * 4) =
          make_float4(s[r][0], s[r][1], s[r][2], s[r][3]);
    }
    __syncthreads();

    // O += P * V
#pragma unroll 16
    for (int j = 0; j < 64; j++) {
      float a0 = Ps[(ty * 4 + 0) * 68 + j];
      float a1 = Ps[(ty * 4 + 1) * 68 + j];
      float a2 = Ps[(ty * 4 + 2) * 68 + j];
      float a3 = Ps[(ty * 4 + 3) * 68 + j];
      float4 bv = *(const float4*)(Vs + j * 64 + tx * 4);
      o[0][0] += a0 * bv.x; o[0][1] += a0 * bv.y; o[0][2] += a0 * bv.z; o[0][3] += a0 * bv.w;
      o[1][0] += a1 * bv.x; o[1][1] += a1 * bv.y; o[1][2] += a1 * bv.z; o[1][3] += a1 * bv.w;
      o[2][0] += a2 * bv.x; o[2][1] += a2 * bv.y; o[2][2] += a2 * bv.z; o[2][3] += a2 * bv.w;
      o[3][0] += a3 * bv.x; o[3][1] += a3 * bv.y; o[3][2] += a3 * bv.z; o[3][3] += a3 * bv.w;
    }
  }

  // Epilogue: normalize and store.
  float* Og = g_att + ((size_t)bh * TT + qb) * HD;
#pragma unroll
  for (int r = 0; r < 4; r++) {
    const float inv = 1.0f / l[r];
    *(float4*)(Og + (size_t)(ty * 4 + r) * HD + tx * 4) =
        make_float4(o[r][0] * inv, o[r][1] * inv, o[r][2] * inv, o[r][3] * inv);
  }
}

// ---------------------------------------------------------------------------
// Kernel 4: output rotation (mat_o) + unpermute to channel-major [B][C][T].
// CTA = (b*nh, t-block of 64). Transpose through smem for coalesced writes.
// ---------------------------------------------------------------------------
__global__ __launch_bounds__(256) void rotary_o_kernel(
    const float* __restrict__ mo) {
  __shared__ float smo[64][65];
  const int bh = blockIdx.y;
  const int b = bh >> 3, nh = bh & 7;
  const int tb = blockIdx.x * 64;
  const int tid = threadIdx.x;
  const float4* src = (const float4*)(g_att + ((size_t)bh * TT + tb) * HD);
#pragma unroll
  for (int i = 0; i < 4; i++) {
    const int pos = tid + i * 256;       // 0..1023 float4s of the tile
    const int trow = pos >> 4;           // token within block
    const int c4 = pos & 15;             // float4 index within row
    float4 v = src[pos];
    const int t = tb + trow;
    const float4* mm = (const float4*)(mo + (size_t)t * 128) + c4 * 2;
    float4 m0 = mm[0], m1 = mm[1];
    smo[trow][c4 * 4 + 0] = m0.x * v.x + m0.y * v.y;
    smo[trow][c4 * 4 + 1] = m0.z * v.x + m0.w * v.y;
    smo[trow][c4 * 4 + 2] = m1.x * v.z + m1.y * v.w;
    smo[trow][c4 * 4 + 3] = m1.z * v.z + m1.w * v.w;
  }
  __syncthreads();
  const int d = tid >> 2;
  const int tseg = tid & 3;
  float* dst = g_orot + ((size_t)b * CC + d * 8 + nh) * TT + tb + tseg * 16;
#pragma unroll
  for (int i = 0; i < 4; i++) {
    const int t0 = tseg * 16 + i * 4;
    *(float4*)(dst + i * 4) = make_float4(smo[t0 + 0][d], smo[t0 + 1][d],
                                          smo[t0 + 2][d], smo[t0 + 3][d]);
  }
}

// ---------------------------------------------------------------------------
// Kernel 5: output projection GEMM, writes d_out directly.
// out[b][oc][t] = sum_c w_o[oc][c] * g_orot[b][c][t] + b_o[oc]
// ---------------------------------------------------------------------------
__global__ __launch_bounds__(256) void oproj_gemm_kernel(
    const float* __restrict__ w, const float* __restrict__ bias,
    float* __restrict__ out) {
  __shared__ float As[16][65];
  __shared__ float Bs[16][64];
  const int b  = blockIdx.z;
  const int bm = blockIdx.y * 64;
  const int bn = blockIdx.x * 64;
  const int tid = threadIdx.x;
  const int tx = tid & 15, ty = tid >> 4;
  const int a_m = tid >> 2;
  const int a_k = (tid & 3) << 2;
  const int b_k = tid >> 4;
  const int b_n = (tid & 15) << 2;
  const float* xb = g_orot + (size_t)b * CC * TT;

  float acc[4][4];
#pragma unroll
  for (int r = 0; r < 4; r++)
#pragma unroll
    for (int c = 0; c < 4; c++) acc[r][c] = 0.f;

  for (int k0 = 0; k0 < CC; k0 += 16) {
    float4 av = *(const float4*)(w + (size_t)(bm + a_m) * CC + k0 + a_k);
    As[a_k + 0][a_m] = av.x;
    As[a_k + 1][a_m] = av.y;
    As[a_k + 2][a_m] = av.z;
    As[a_k + 3][a_m] = av.w;
    *(float4*)(&Bs[b_k][b_n]) =
        *(const float4*)(xb + (size_t)(k0 + b_k) * TT + bn + b_n);
    __syncthreads();
#pragma unroll
    for (int k = 0; k < 16; k++) {
      float a0 = As[k][ty * 4 + 0];
      float a1 = As[k][ty * 4 + 1];
      float a2 = As[k][ty * 4 + 2];
      float a3 = As[k][ty * 4 + 3];
      float4 bv = *(const float4*)(&Bs[k][tx * 4]);
      acc[0][0] += a0 * bv.x; acc[0][1] += a0 * bv.y;
      acc[0][2] += a0 * bv.z; acc[0][3] += a0 * bv.w;
      acc[1][0] += a1 * bv.x; acc[1][1] += a1 * bv.y;
      acc[1][2] += a1 * bv.z; acc[1][3] += a1 * bv.w;
      acc[2][0] += a2 * bv.x; acc[2][1] += a2 * bv.y;
      acc[2][2] += a2 * bv.z; acc[2][3] += a2 * bv.w;
      acc[3][0] += a3 * bv.x; acc[3][1] += a3 * bv.y;
      acc[3][2] += a3 * bv.z; acc[3][3] += a3 * bv.w;
    }
    __syncthreads();
  }

#pragma unroll
  for (int r = 0; r < 4; r++) {
    const int oc = bm + ty * 4 + r;
    const float bi = __ldg(bias + oc);
    float* dst = out + ((size_t)b * CC + oc) * TT + bn + tx * 4;
    *(float4*)dst = make_float4(acc[r][0] + bi, acc[r][1] + bi,
                                acc[r][2] + bi, acc[r][3] + bi);
  }
}

// ---------------------------------------------------------------------------
// Launch: x, w_qkv, b_qkv, w_o, b_o, mat_q, mat_k, mat_v, mat_o
// ---------------------------------------------------------------------------
extern "C" void kernel_launch(void* const* d_in, const int* in_sizes, int n_in,
                              void* d_out, int out_size) {
  const float* x     = (const float*)d_in[0];
  const float* w_qkv = (const float*)d_in[1];
  const float* b_qkv = (const float*)d_in[2];
  const float* w_o   = (const float*)d_in[3];
  const float* b_o   = (const float*)d_in[4];
  const float* mat_q = (const float*)d_in[5];
  const float* mat_k = (const float*)d_in[6];
  const float* mat_v = (const float*)d_in[7];
  const float* mat_o = (const float*)d_in[8];
  float* out = (float*)d_out;

  // QKV projection: grid (t-tiles, o-tiles, batch)
  qkv_gemm_kernel<<<dim3(TT / 64, (3 * CC) / 64, BB), 256>>>(x, w_qkv, b_qkv);

  // Rotary on q, k, v (in place)
  rotary_qkv_kernel<<<dim3((BB * NH * TT) / 128, 3), 128>>>(mat_q, mat_k, mat_v);

  // Attention
  const int ATTN_SMEM = (64 * 64 + 64 * 65 + 64 * 64 + 64 * 68) * (int)sizeof(float);
  cudaFuncSetAttribute(attn_kernel, cudaFuncAttributeMaxDynamicSharedMemorySize,
                       ATTN_SMEM);
  attn_kernel<<<dim3(TT / 64, BB * NH), 256, ATTN_SMEM>>>();

  // Output rotary + unpermute to channel-major
  rotary_o_kernel<<<dim3(TT / 64, BB * NH), 256>>>(mat_o);

  // Output projection into d_out
  oproj_gemm_kernel<<<dim3(TT / 64, CC / 64, BB), 256>>>(w_o, b_o, out);
}